// round 9
// baseline (speedup 1.0000x reference)
#include <cuda_runtime.h>
#include <cuda_bf16.h>
#include <mma.h>
#include <cstdint>

using namespace nvcuda;

#define B_ 16
#define N_ 1024
#define C_ 768
#define E_ 8
#define H_ 192
#define D_ 4
#define K_ 2

// ---------------- device scratch (no runtime allocation allowed) -------------
__device__ __nv_bfloat16 g_xbf[B_ * N_ * C_];     // x in bf16
__device__ __nv_bfloat16 g_w1bf[E_ * H_ * C_];    // fc1_w bf16 [E][H][C]
__device__ __nv_bfloat16 g_w2bf[E_ * C_ * H_];    // fc2_w bf16 [E][C][H]
__device__ float g_part[B_ * 8 * E_];
__device__ int   g_sel[B_ * K_];
__device__ float g_gv[B_ * K_];

// ---------------- merged prep kernel: gate (blocks 0..127) + convert (rest) ---
// gate part and convert part are the R3-measured versions, fused into one
// launch so they overlap instead of running serially.
__global__ __launch_bounds__(128)
void prep_kernel(const float* __restrict__ x,
                 const int* __restrict__ task_ids,
                 const float* __restrict__ eps,
                 const float* __restrict__ gate_w,
                 const float* __restrict__ w1,
                 const float* __restrict__ w2) {
    if (blockIdx.x >= 128) {
        // -------- convert role (1024 blocks x 128 threads, grid-stride) ------
        int i = (blockIdx.x - 128) * 128 + threadIdx.x;
        int stride = 1024 * 128;
        const int nx4 = B_ * N_ * C_ / 4;
        const int nw4 = E_ * H_ * C_ / 4;
        for (int t = i; t < nx4; t += stride) {
            float4 v = ((const float4*)x)[t];
            g_xbf[4 * t + 0] = __float2bfloat16(v.x);
            g_xbf[4 * t + 1] = __float2bfloat16(v.y);
            g_xbf[4 * t + 2] = __float2bfloat16(v.z);
            g_xbf[4 * t + 3] = __float2bfloat16(v.w);
        }
        for (int t = i; t < nw4; t += stride) {
            float4 v = ((const float4*)w1)[t];
            g_w1bf[4 * t + 0] = __float2bfloat16(v.x);
            g_w1bf[4 * t + 1] = __float2bfloat16(v.y);
            g_w1bf[4 * t + 2] = __float2bfloat16(v.z);
            g_w1bf[4 * t + 3] = __float2bfloat16(v.w);
        }
        for (int t = i; t < nw4; t += stride) {
            float4 v = ((const float4*)w2)[t];
            g_w2bf[4 * t + 0] = __float2bfloat16(v.x);
            g_w2bf[4 * t + 1] = __float2bfloat16(v.y);
            g_w2bf[4 * t + 2] = __float2bfloat16(v.z);
            g_w2bf[4 * t + 3] = __float2bfloat16(v.w);
        }
        return;
    }

    // -------- gate role (blocks 0..127; R3 gate verbatim) --------------------
    extern __shared__ float s_gw[];            // [C_*16]
    __shared__ float s_red[4 * E_];
    int b = blockIdx.x >> 3;
    int by = blockIdx.x & 7;
    int n = by * 128 + threadIdx.x;
    int task = task_ids[b];

    const float4* gw4 = (const float4*)(gate_w + (size_t)task * C_ * 16);
    for (int i = threadIdx.x; i < C_ * 16 / 4; i += 128)
        ((float4*)s_gw)[i] = gw4[i];
    __syncthreads();

    float acc[16];
#pragma unroll
    for (int e = 0; e < 16; e++) acc[e] = 0.f;

    const float* xr = x + ((size_t)b * N_ + n) * C_;
    for (int c = 0; c < C_; c += 4) {
        float4 xv = *(const float4*)(xr + c);
#pragma unroll
        for (int e = 0; e < 16; e++) {
            acc[e] += xv.x * s_gw[(c + 0) * 16 + e];
            acc[e] += xv.y * s_gw[(c + 1) * 16 + e];
            acc[e] += xv.z * s_gw[(c + 2) * 16 + e];
            acc[e] += xv.w * s_gw[(c + 3) * 16 + e];
        }
    }

    float lg[E_];
    const float* er = eps + ((size_t)b * N_ + n) * E_;
#pragma unroll
    for (int e = 0; e < E_; e++) {
        float raw = acc[E_ + e];
        float sp = (raw > 15.f) ? raw : log1pf(expf(raw));
        lg[e] = acc[e] + er[e] * (sp + 0.01f);
    }

#pragma unroll
    for (int off = 16; off > 0; off >>= 1) {
#pragma unroll
        for (int e = 0; e < E_; e++)
            lg[e] += __shfl_down_sync(0xffffffffu, lg[e], off);
    }
    int warp = threadIdx.x >> 5, lane = threadIdx.x & 31;
    if (lane == 0) {
#pragma unroll
        for (int e = 0; e < E_; e++) s_red[warp * E_ + e] = lg[e];
    }
    __syncthreads();
    if (threadIdx.x < E_) {
        float s = s_red[threadIdx.x] + s_red[E_ + threadIdx.x] +
                  s_red[2 * E_ + threadIdx.x] + s_red[3 * E_ + threadIdx.x];
        g_part[((size_t)b * 8 + by) * E_ + threadIdx.x] = s;
    }
}

// ---------------- top-2 + softmax ---------------------------------------------
__global__ void topk_kernel() {
    int b = threadIdx.x;
    if (b >= B_) return;
    float s[E_];
#pragma unroll
    for (int e = 0; e < E_; e++) {
        float acc = 0.f;
        for (int blk = 0; blk < 8; blk++) acc += g_part[(b * 8 + blk) * E_ + e];
        s[e] = acc;
    }
    int i1 = 0;
#pragma unroll
    for (int e = 1; e < E_; e++) if (s[e] > s[i1]) i1 = e;
    int i2 = (i1 == 0) ? 1 : 0;
#pragma unroll
    for (int e = 0; e < E_; e++) if (e != i1 && s[e] > s[i2]) i2 = e;
    float v1 = s[i1], v2 = s[i2];
    float sc = (v1 - v2) / ((v1 - v2) + 1e-6f);
    float e1 = expf(sc);
    g_sel[b * 2 + 0] = i1;
    g_sel[b * 2 + 1] = i2;
    g_gv[b * 2 + 0] = e1 / (e1 + 1.f);
    g_gv[b * 2 + 1] = 1.f / (e1 + 1.f);
}

// ---------------- fused 2-expert adapter kernel (R3, measured 113.8us) --------
#define TM 128                 // rows per block
#define KC 64                  // k chunk (phase 1)
#define PA 72                  // smem pitch for A/B1 tiles (bf16 elems)
#define PH 200                 // smem pitch for h / B2 tiles (bf16 elems)
#define PF 132                 // smem pitch for f32 epilogue staging
#define PS 100                 // smem pitch for f32 phase-1 staging

// smem layout (bytes):
#define OFF_H0   0
#define OFF_H1   51200                       // 128*200*2
#define OFF_AB   102400
#define OFF_A0   (OFF_AB)
#define OFF_A1   (OFF_AB + 18432)            // 128*72*2
#define OFF_B0   (OFF_AB + 36864)
#define OFF_B1   (OFF_AB + 36864 + 27648)    // 192*72*2
#define SMEM_TOTAL (OFF_AB + 92160)          // 194560

__device__ __forceinline__ void cpasync16(void* dst, const void* src) {
    unsigned int d = (unsigned int)__cvta_generic_to_shared(dst);
    asm volatile("cp.async.cg.shared.global [%0], [%1], 16;\n" :: "r"(d), "l"(src));
}
__device__ __forceinline__ void cpcommit() {
    asm volatile("cp.async.commit_group;\n");
}
template <int Nw>
__device__ __forceinline__ void cpwait() {
    asm volatile("cp.async.wait_group %0;\n" :: "n"(Nw));
}

__global__ __launch_bounds__(256, 1)
void expert_kernel(const float* __restrict__ x,
                   const float* __restrict__ b1,
                   const float* __restrict__ b2,
                   float* __restrict__ out) {
    extern __shared__ char smem[];
    __nv_bfloat16* s_h[2] = { (__nv_bfloat16*)(smem + OFF_H0),
                              (__nv_bfloat16*)(smem + OFF_H1) };
    __nv_bfloat16* s_a[2] = { (__nv_bfloat16*)(smem + OFF_A0),
                              (__nv_bfloat16*)(smem + OFF_A1) };
    __nv_bfloat16* s_b[2] = { (__nv_bfloat16*)(smem + OFF_B0),
                              (__nv_bfloat16*)(smem + OFF_B1) };
    __nv_bfloat16* s_b2 = (__nv_bfloat16*)(smem + OFF_AB);   // phase2 W2 tile [128][PH]
    float* s_f = (float*)(smem + OFF_AB);                    // phase2 staging [128][PF]

    const int b = blockIdx.x;
    const int row0 = blockIdx.y * TM;
    const int tid = threadIdx.x;
    const int w = tid >> 5;
    const int r = w >> 1;       // row quarter (32 rows each)
    const int hw = w & 1;       // column half

    const int e0 = g_sel[b * 2 + 0], e1 = g_sel[b * 2 + 1];
    const float g0 = g_gv[b * 2 + 0], g1 = g_gv[b * 2 + 1];
    const int eid[2] = { e0, e1 };
    const float gg[2] = { g0, g1 };

    // ================= phase 1: h_e = g_e * gelu(x @ W1_e^T + b1_e) ==========
    for (int ke = 0; ke < 2; ke++) {
        const int e = eid[ke];
        const __nv_bfloat16* xsrc = g_xbf + ((size_t)(b * N_ + row0)) * C_;
        const __nv_bfloat16* wsrc = g_w1bf + (size_t)e * H_ * C_;

        // preload chunk 0
        {
#pragma unroll
            for (int i = 0; i < 4; i++) {
                int seg = tid + i * 256;                 // 0..1023
                int row = seg >> 3, so = (seg & 7) * 8;
                cpasync16(s_a[0] + row * PA + so, xsrc + (size_t)row * C_ + so);
            }
#pragma unroll
            for (int i = 0; i < 6; i++) {
                int seg = tid + i * 256;                 // 0..1535
                int row = seg >> 3, so = (seg & 7) * 8;
                cpasync16(s_b[0] + row * PA + so, wsrc + (size_t)row * C_ + so);
            }
            cpcommit();
        }

        wmma::fragment<wmma::accumulator, 16, 16, 16, float> acc[2][6];
#pragma unroll
        for (int i = 0; i < 2; i++)
#pragma unroll
            for (int j = 0; j < 6; j++) wmma::fill_fragment(acc[i][j], 0.f);

        for (int t = 0; t < C_ / KC; t++) {
            int cur = t & 1;
            if (t + 1 < C_ / KC) {
                int nxt = cur ^ 1, kc = (t + 1) * KC;
#pragma unroll
                for (int i = 0; i < 4; i++) {
                    int seg = tid + i * 256;
                    int row = seg >> 3, so = (seg & 7) * 8;
                    cpasync16(s_a[nxt] + row * PA + so, xsrc + (size_t)row * C_ + kc + so);
                }
#pragma unroll
                for (int i = 0; i < 6; i++) {
                    int seg = tid + i * 256;
                    int row = seg >> 3, so = (seg & 7) * 8;
                    cpasync16(s_b[nxt] + row * PA + so, wsrc + (size_t)row * C_ + kc + so);
                }
                cpcommit();
                cpwait<1>();
            } else {
                cpwait<0>();
            }
            __syncthreads();

#pragma unroll
            for (int kk = 0; kk < KC / 16; kk++) {
                wmma::fragment<wmma::matrix_a, 16, 16, 16, __nv_bfloat16, wmma::row_major> aF[2];
#pragma unroll
                for (int i = 0; i < 2; i++)
                    wmma::load_matrix_sync(aF[i], s_a[cur] + (r * 32 + i * 16) * PA + kk * 16, PA);
#pragma unroll
                for (int j = 0; j < 6; j++) {
                    wmma::fragment<wmma::matrix_b, 16, 16, 16, __nv_bfloat16, wmma::col_major> bF;
                    wmma::load_matrix_sync(bF, s_b[cur] + (hw * 96 + j * 16) * PA + kk * 16, PA);
#pragma unroll
                    for (int i = 0; i < 2; i++)
                        wmma::mma_sync(acc[i][j], aF[i], bF, acc[i][j]);
                }
            }
            __syncthreads();
        }

        // stage -> bias + gelu + gate-scale -> bf16 into s_h[ke]
        // staging region: for ke==0 use s_h[1] space (free), for ke==1 use s_ab (free).
        float* stg = (ke == 0) ? (float*)(smem + OFF_H1) : (float*)(smem + OFF_AB);
        const float gsc = gg[ke];
#pragma unroll
        for (int half = 0; half < 2; half++) {
            if (hw == half) {
#pragma unroll
                for (int i = 0; i < 2; i++)
#pragma unroll
                    for (int j = 0; j < 6; j++)
                        wmma::store_matrix_sync(stg + (r * 32 + i * 16) * PS + j * 16,
                                                acc[i][j], PS, wmma::mem_row_major);
            }
            __syncthreads();
            for (int idx = tid; idx < TM * 96; idx += 256) {
                int n = idx / 96, hh = idx % 96;
                int hcol = half * 96 + hh;
                float v = stg[n * PS + hh] + b1[e * H_ + hcol];
                float gel = 0.5f * v * (1.f + erff(v * 0.70710678118f));
                s_h[ke][n * PH + hcol] = __float2bfloat16(gsc * gel);
            }
            __syncthreads();
        }
    }

    // ================= phase 2: out = x + sum_e h_e @ W2_e^T + bias ==========
    for (int cc = 0; cc < C_; cc += 128) {
        wmma::fragment<wmma::accumulator, 16, 16, 16, float> acc2[2][4];
#pragma unroll
        for (int i = 0; i < 2; i++)
#pragma unroll
            for (int j = 0; j < 4; j++) wmma::fill_fragment(acc2[i][j], 0.f);

        for (int ke = 0; ke < 2; ke++) {
            const int e = eid[ke];
            __syncthreads();   // s_ab free (prev epilogue / prev expert k-loop done)
            const __nv_bfloat16* wsrc = g_w2bf + (size_t)e * C_ * H_ + (size_t)cc * H_;
            // [128 rows of W2 (C-dim)] x [H_=192 elems] = 128*24 segs of 8 elems
#pragma unroll
            for (int i = 0; i < 12; i++) {
                int seg = tid + i * 256;                 // 0..3071
                int row = seg / 24, so = (seg % 24) * 8;
                cpasync16(s_b2 + row * PH + so, wsrc + (size_t)row * H_ + so);
            }
            cpcommit();
            cpwait<0>();
            __syncthreads();

#pragma unroll
            for (int kk = 0; kk < H_ / 16; kk++) {
                wmma::fragment<wmma::matrix_a, 16, 16, 16, __nv_bfloat16, wmma::row_major> aF[2];
#pragma unroll
                for (int i = 0; i < 2; i++)
                    wmma::load_matrix_sync(aF[i], s_h[ke] + (r * 32 + i * 16) * PH + kk * 16, PH);
#pragma unroll
                for (int j = 0; j < 4; j++) {
                    wmma::fragment<wmma::matrix_b, 16, 16, 16, __nv_bfloat16, wmma::col_major> bF;
                    wmma::load_matrix_sync(bF, s_b2 + (hw * 64 + j * 16) * PH + kk * 16, PH);
#pragma unroll
                    for (int i = 0; i < 2; i++)
                        wmma::mma_sync(acc2[i][j], aF[i], bF, acc2[i][j]);
                }
            }
        }
        __syncthreads();
#pragma unroll
        for (int i = 0; i < 2; i++)
#pragma unroll
            for (int j = 0; j < 4; j++)
                wmma::store_matrix_sync(s_f + (r * 32 + i * 16) * PF + hw * 64 + j * 16,
                                        acc2[i][j], PF, wmma::mem_row_major);
        __syncthreads();

#pragma unroll
        for (int it = 0; it < 16; it++) {
            int idx = tid + it * 256;                    // 0..4095
            int row = idx >> 5, q = idx & 31;
            int c = cc + q * 4;
            size_t o = ((size_t)(b * N_ + row0 + row)) * C_ + c;
            float4 xv = *(const float4*)(x + o);
            float4 res;
            res.x = s_f[row * PF + q * 4 + 0] + g0 * b2[e0 * C_ + c + 0] + g1 * b2[e1 * C_ + c + 0] + xv.x;
            res.y = s_f[row * PF + q * 4 + 1] + g0 * b2[e0 * C_ + c + 1] + g1 * b2[e1 * C_ + c + 1] + xv.y;
            res.z = s_f[row * PF + q * 4 + 2] + g0 * b2[e0 * C_ + c + 2] + g1 * b2[e1 * C_ + c + 2] + xv.z;
            res.w = s_f[row * PF + q * 4 + 3] + g0 * b2[e0 * C_ + c + 3] + g1 * b2[e1 * C_ + c + 3] + xv.w;
            *(float4*)(out + o) = res;
        }
        __syncthreads();
    }
}

// ---------------- launch ------------------------------------------------------
extern "C" void kernel_launch(void* const* d_in, const int* in_sizes, int n_in,
                              void* d_out, int out_size) {
    const float* x        = (const float*)d_in[0];
    const int*   task_ids = (const int*)d_in[1];
    const float* eps      = (const float*)d_in[2];
    const float* gate_w   = (const float*)d_in[3];
    const float* fc1_w    = (const float*)d_in[4];
    const float* fc1_b    = (const float*)d_in[5];
    const float* fc2_w    = (const float*)d_in[6];
    const float* fc2_b    = (const float*)d_in[7];
    float* out = (float*)d_out;

    cudaFuncSetAttribute(expert_kernel, cudaFuncAttributeMaxDynamicSharedMemorySize, SMEM_TOTAL);
    cudaFuncSetAttribute(prep_kernel, cudaFuncAttributeMaxDynamicSharedMemorySize, C_ * 16 * 4);

    // blocks 0..127: gate; blocks 128..1151: x/w1/w2 -> bf16 conversion
    prep_kernel<<<1152, 128, C_ * 16 * 4>>>(x, task_ids, eps, gate_w, fc1_w, fc2_w);
    topk_kernel<<<1, 32>>>();
    expert_kernel<<<dim3(B_, N_ / TM), 256, SMEM_TOTAL>>>(x, fc1_b, fc2_b, out);
}

// round 10
// speedup vs baseline: 1.0325x; 1.0325x over previous
#include <cuda_runtime.h>
#include <cuda_bf16.h>
#include <mma.h>
#include <cstdint>

using namespace nvcuda;

#define B_ 16
#define N_ 1024
#define C_ 768
#define E_ 8
#define H_ 192
#define D_ 4
#define K_ 2

// ---------------- device scratch (no runtime allocation allowed) -------------
__device__ __nv_bfloat16 g_xbf[B_ * N_ * C_];     // x in bf16 (written by gate)
__device__ __nv_bfloat16 g_w1bf[E_ * H_ * C_];    // fc1_w bf16 [E][H][C]
__device__ __nv_bfloat16 g_w2bf[E_ * C_ * H_];    // fc2_w bf16 [E][C][H]
__device__ float g_part[B_ * 8 * E_];

// ---------------- fp32 -> bf16 conversion (weights only) ----------------------
__global__ void convert_kernel(const float* __restrict__ w1,
                               const float* __restrict__ w2) {
    int i = blockIdx.x * blockDim.x + threadIdx.x;
    int stride = gridDim.x * blockDim.x;
    const int nw4 = E_ * H_ * C_ / 4;
    for (int t = i; t < nw4; t += stride) {
        float4 v = ((const float4*)w1)[t];
        g_w1bf[4 * t + 0] = __float2bfloat16(v.x);
        g_w1bf[4 * t + 1] = __float2bfloat16(v.y);
        g_w1bf[4 * t + 2] = __float2bfloat16(v.z);
        g_w1bf[4 * t + 3] = __float2bfloat16(v.w);
    }
    for (int t = i; t < nw4; t += stride) {
        float4 v = ((const float4*)w2)[t];
        g_w2bf[4 * t + 0] = __float2bfloat16(v.x);
        g_w2bf[4 * t + 1] = __float2bfloat16(v.y);
        g_w2bf[4 * t + 2] = __float2bfloat16(v.z);
        g_w2bf[4 * t + 3] = __float2bfloat16(v.w);
    }
}

// ---------------- gate kernel (R3 gating + coalesced x->bf16 pass) ------------
__global__ void gate_kernel(const float* __restrict__ x,
                            const int* __restrict__ task_ids,
                            const float* __restrict__ eps,
                            const float* __restrict__ gate_w) {
    extern __shared__ float s_gw[];            // [C_*16]
    __shared__ float s_red[4 * E_];
    int b = blockIdx.x;
    int by = blockIdx.y;
    int n = by * 128 + threadIdx.x;
    int task = task_ids[b];

    const float4* gw4 = (const float4*)(gate_w + (size_t)task * C_ * 16);
    for (int i = threadIdx.x; i < C_ * 16 / 4; i += 128)
        ((float4*)s_gw)[i] = gw4[i];

    // coalesced bf16 conversion of this block's 128 rows of x
    {
        const float4* xblk = (const float4*)(x + ((size_t)(b * N_ + by * 128)) * C_);
        uint2* xbblk = (uint2*)(g_xbf + ((size_t)(b * N_ + by * 128)) * C_);
        const int tot = 128 * C_ / 4;
        for (int idx = threadIdx.x; idx < tot; idx += 128) {
            float4 v = xblk[idx];
            __nv_bfloat162 p0, p1;
            p0.x = __float2bfloat16(v.x); p0.y = __float2bfloat16(v.y);
            p1.x = __float2bfloat16(v.z); p1.y = __float2bfloat16(v.w);
            uint2 st;
            st.x = *reinterpret_cast<unsigned int*>(&p0);
            st.y = *reinterpret_cast<unsigned int*>(&p1);
            xbblk[idx] = st;
        }
    }
    __syncthreads();

    float acc[16];
#pragma unroll
    for (int e = 0; e < 16; e++) acc[e] = 0.f;

    const float* xr = x + ((size_t)b * N_ + n) * C_;
    for (int c = 0; c < C_; c += 4) {
        float4 xv = *(const float4*)(xr + c);
#pragma unroll
        for (int e = 0; e < 16; e++) {
            acc[e] += xv.x * s_gw[(c + 0) * 16 + e];
            acc[e] += xv.y * s_gw[(c + 1) * 16 + e];
            acc[e] += xv.z * s_gw[(c + 2) * 16 + e];
            acc[e] += xv.w * s_gw[(c + 3) * 16 + e];
        }
    }

    float lg[E_];
    const float* er = eps + ((size_t)b * N_ + n) * E_;
#pragma unroll
    for (int e = 0; e < E_; e++) {
        float raw = acc[E_ + e];
        float sp = (raw > 15.f) ? raw : log1pf(expf(raw));
        lg[e] = acc[e] + er[e] * (sp + 0.01f);
    }

#pragma unroll
    for (int off = 16; off > 0; off >>= 1) {
#pragma unroll
        for (int e = 0; e < E_; e++)
            lg[e] += __shfl_down_sync(0xffffffffu, lg[e], off);
    }
    int warp = threadIdx.x >> 5, lane = threadIdx.x & 31;
    if (lane == 0) {
#pragma unroll
        for (int e = 0; e < E_; e++) s_red[warp * E_ + e] = lg[e];
    }
    __syncthreads();
    if (threadIdx.x < E_) {
        float s = s_red[threadIdx.x] + s_red[E_ + threadIdx.x] +
                  s_red[2 * E_ + threadIdx.x] + s_red[3 * E_ + threadIdx.x];
        g_part[((size_t)b * 8 + by) * E_ + threadIdx.x] = s;
    }
}

// ---------------- fused 2-expert adapter kernel (R3 + inline top-2) -----------
#define TM 128                 // rows per block
#define KC 64                  // k chunk (phase 1)
#define PA 72                  // smem pitch for A/B1 tiles (bf16 elems)
#define PH 200                 // smem pitch for h / B2 tiles (bf16 elems)
#define PF 132                 // smem pitch for f32 epilogue staging
#define PS 100                 // smem pitch for f32 phase-1 staging

// smem layout (bytes):
#define OFF_H0   0
#define OFF_H1   51200                       // 128*200*2
#define OFF_AB   102400
#define OFF_A0   (OFF_AB)
#define OFF_A1   (OFF_AB + 18432)            // 128*72*2
#define OFF_B0   (OFF_AB + 36864)
#define OFF_B1   (OFF_AB + 36864 + 27648)    // 192*72*2
#define SMEM_TOTAL (OFF_AB + 92160)          // 194560

__device__ __forceinline__ void cpasync16(void* dst, const void* src) {
    unsigned int d = (unsigned int)__cvta_generic_to_shared(dst);
    asm volatile("cp.async.cg.shared.global [%0], [%1], 16;\n" :: "r"(d), "l"(src));
}
__device__ __forceinline__ void cpcommit() {
    asm volatile("cp.async.commit_group;\n");
}
template <int Nw>
__device__ __forceinline__ void cpwait() {
    asm volatile("cp.async.wait_group %0;\n" :: "n"(Nw));
}

__global__ __launch_bounds__(256, 1)
void expert_kernel(const float* __restrict__ x,
                   const float* __restrict__ b1,
                   const float* __restrict__ b2,
                   float* __restrict__ out) {
    extern __shared__ char smem[];
    __nv_bfloat16* s_h[2] = { (__nv_bfloat16*)(smem + OFF_H0),
                              (__nv_bfloat16*)(smem + OFF_H1) };
    __nv_bfloat16* s_a[2] = { (__nv_bfloat16*)(smem + OFF_A0),
                              (__nv_bfloat16*)(smem + OFF_A1) };
    __nv_bfloat16* s_b[2] = { (__nv_bfloat16*)(smem + OFF_B0),
                              (__nv_bfloat16*)(smem + OFF_B1) };
    __nv_bfloat16* s_b2 = (__nv_bfloat16*)(smem + OFF_AB);   // phase2 W2 tile [128][PH]
    float* s_f = (float*)(smem + OFF_AB);                    // phase2 staging [128][PF]

    __shared__ int   s_sel[2];
    __shared__ float s_gvs[2];

    const int b = blockIdx.x;
    const int row0 = blockIdx.y * TM;
    const int tid = threadIdx.x;
    const int w = tid >> 5;
    const int r = w >> 1;       // row quarter (32 rows each)
    const int hw = w & 1;       // column half

    // inline top-2 + softmax (replaces separate topk kernel)
    if (tid == 0) {
        float s[E_];
#pragma unroll
        for (int e = 0; e < E_; e++) {
            float a = 0.f;
#pragma unroll
            for (int blk = 0; blk < 8; blk++) a += g_part[(b * 8 + blk) * E_ + e];
            s[e] = a;
        }
        int i1 = 0;
#pragma unroll
        for (int e = 1; e < E_; e++) if (s[e] > s[i1]) i1 = e;
        int i2 = (i1 == 0) ? 1 : 0;
#pragma unroll
        for (int e = 0; e < E_; e++) if (e != i1 && s[e] > s[i2]) i2 = e;
        float v1 = s[i1], v2 = s[i2];
        float sc = (v1 - v2) / ((v1 - v2) + 1e-6f);
        float e1 = expf(sc);
        s_sel[0] = i1;
        s_sel[1] = i2;
        s_gvs[0] = e1 / (e1 + 1.f);
        s_gvs[1] = 1.f / (e1 + 1.f);
    }
    __syncthreads();

    const int e0 = s_sel[0], e1 = s_sel[1];
    const float g0 = s_gvs[0], g1 = s_gvs[1];
    const int eid[2] = { e0, e1 };
    const float gg[2] = { g0, g1 };

    // ================= phase 1: h_e = g_e * gelu(x @ W1_e^T + b1_e) ==========
    for (int ke = 0; ke < 2; ke++) {
        const int e = eid[ke];
        const __nv_bfloat16* xsrc = g_xbf + ((size_t)(b * N_ + row0)) * C_;
        const __nv_bfloat16* wsrc = g_w1bf + (size_t)e * H_ * C_;

        // preload chunk 0
        {
#pragma unroll
            for (int i = 0; i < 4; i++) {
                int seg = tid + i * 256;                 // 0..1023
                int row = seg >> 3, so = (seg & 7) * 8;
                cpasync16(s_a[0] + row * PA + so, xsrc + (size_t)row * C_ + so);
            }
#pragma unroll
            for (int i = 0; i < 6; i++) {
                int seg = tid + i * 256;                 // 0..1535
                int row = seg >> 3, so = (seg & 7) * 8;
                cpasync16(s_b[0] + row * PA + so, wsrc + (size_t)row * C_ + so);
            }
            cpcommit();
        }

        wmma::fragment<wmma::accumulator, 16, 16, 16, float> acc[2][6];
#pragma unroll
        for (int i = 0; i < 2; i++)
#pragma unroll
            for (int j = 0; j < 6; j++) wmma::fill_fragment(acc[i][j], 0.f);

        for (int t = 0; t < C_ / KC; t++) {
            int cur = t & 1;
            if (t + 1 < C_ / KC) {
                int nxt = cur ^ 1, kc = (t + 1) * KC;
#pragma unroll
                for (int i = 0; i < 4; i++) {
                    int seg = tid + i * 256;
                    int row = seg >> 3, so = (seg & 7) * 8;
                    cpasync16(s_a[nxt] + row * PA + so, xsrc + (size_t)row * C_ + kc + so);
                }
#pragma unroll
                for (int i = 0; i < 6; i++) {
                    int seg = tid + i * 256;
                    int row = seg >> 3, so = (seg & 7) * 8;
                    cpasync16(s_b[nxt] + row * PA + so, wsrc + (size_t)row * C_ + kc + so);
                }
                cpcommit();
                cpwait<1>();
            } else {
                cpwait<0>();
            }
            __syncthreads();

#pragma unroll
            for (int kk = 0; kk < KC / 16; kk++) {
                wmma::fragment<wmma::matrix_a, 16, 16, 16, __nv_bfloat16, wmma::row_major> aF[2];
#pragma unroll
                for (int i = 0; i < 2; i++)
                    wmma::load_matrix_sync(aF[i], s_a[cur] + (r * 32 + i * 16) * PA + kk * 16, PA);
#pragma unroll
                for (int j = 0; j < 6; j++) {
                    wmma::fragment<wmma::matrix_b, 16, 16, 16, __nv_bfloat16, wmma::col_major> bF;
                    wmma::load_matrix_sync(bF, s_b[cur] + (hw * 96 + j * 16) * PA + kk * 16, PA);
#pragma unroll
                    for (int i = 0; i < 2; i++)
                        wmma::mma_sync(acc[i][j], aF[i], bF, acc[i][j]);
                }
            }
            __syncthreads();
        }

        // stage -> bias + gelu + gate-scale -> bf16 into s_h[ke]
        float* stg = (ke == 0) ? (float*)(smem + OFF_H1) : (float*)(smem + OFF_AB);
        const float gsc = gg[ke];
#pragma unroll
        for (int half = 0; half < 2; half++) {
            if (hw == half) {
#pragma unroll
                for (int i = 0; i < 2; i++)
#pragma unroll
                    for (int j = 0; j < 6; j++)
                        wmma::store_matrix_sync(stg + (r * 32 + i * 16) * PS + j * 16,
                                                acc[i][j], PS, wmma::mem_row_major);
            }
            __syncthreads();
            for (int idx = tid; idx < TM * 96; idx += 256) {
                int n = idx / 96, hh = idx % 96;
                int hcol = half * 96 + hh;
                float v = stg[n * PS + hh] + b1[e * H_ + hcol];
                float gel = 0.5f * v * (1.f + erff(v * 0.70710678118f));
                s_h[ke][n * PH + hcol] = __float2bfloat16(gsc * gel);
            }
            __syncthreads();
        }
    }

    // ================= phase 2: out = x + sum_e h_e @ W2_e^T + bias ==========
    for (int cc = 0; cc < C_; cc += 128) {
        wmma::fragment<wmma::accumulator, 16, 16, 16, float> acc2[2][4];
#pragma unroll
        for (int i = 0; i < 2; i++)
#pragma unroll
            for (int j = 0; j < 4; j++) wmma::fill_fragment(acc2[i][j], 0.f);

        for (int ke = 0; ke < 2; ke++) {
            const int e = eid[ke];
            __syncthreads();   // s_ab free (prev epilogue / prev expert k-loop done)
            const __nv_bfloat16* wsrc = g_w2bf + (size_t)e * C_ * H_ + (size_t)cc * H_;
#pragma unroll
            for (int i = 0; i < 12; i++) {
                int seg = tid + i * 256;                 // 0..3071
                int row = seg / 24, so = (seg % 24) * 8;
                cpasync16(s_b2 + row * PH + so, wsrc + (size_t)row * H_ + so);
            }
            cpcommit();
            cpwait<0>();
            __syncthreads();

#pragma unroll
            for (int kk = 0; kk < H_ / 16; kk++) {
                wmma::fragment<wmma::matrix_a, 16, 16, 16, __nv_bfloat16, wmma::row_major> aF[2];
#pragma unroll
                for (int i = 0; i < 2; i++)
                    wmma::load_matrix_sync(aF[i], s_h[ke] + (r * 32 + i * 16) * PH + kk * 16, PH);
#pragma unroll
                for (int j = 0; j < 4; j++) {
                    wmma::fragment<wmma::matrix_b, 16, 16, 16, __nv_bfloat16, wmma::col_major> bF;
                    wmma::load_matrix_sync(bF, s_b2 + (hw * 64 + j * 16) * PH + kk * 16, PH);
#pragma unroll
                    for (int i = 0; i < 2; i++)
                        wmma::mma_sync(acc2[i][j], aF[i], bF, acc2[i][j]);
                }
            }
        }
        __syncthreads();
#pragma unroll
        for (int i = 0; i < 2; i++)
#pragma unroll
            for (int j = 0; j < 4; j++)
                wmma::store_matrix_sync(s_f + (r * 32 + i * 16) * PF + hw * 64 + j * 16,
                                        acc2[i][j], PF, wmma::mem_row_major);
        __syncthreads();

#pragma unroll
        for (int it = 0; it < 16; it++) {
            int idx = tid + it * 256;                    // 0..4095
            int row = idx >> 5, q = idx & 31;
            int c = cc + q * 4;
            size_t o = ((size_t)(b * N_ + row0 + row)) * C_ + c;
            float4 xv = *(const float4*)(x + o);
            float4 res;
            res.x = s_f[row * PF + q * 4 + 0] + g0 * b2[e0 * C_ + c + 0] + g1 * b2[e1 * C_ + c + 0] + xv.x;
            res.y = s_f[row * PF + q * 4 + 1] + g0 * b2[e0 * C_ + c + 1] + g1 * b2[e1 * C_ + c + 1] + xv.y;
            res.z = s_f[row * PF + q * 4 + 2] + g0 * b2[e0 * C_ + c + 2] + g1 * b2[e1 * C_ + c + 2] + xv.z;
            res.w = s_f[row * PF + q * 4 + 3] + g0 * b2[e0 * C_ + c + 3] + g1 * b2[e1 * C_ + c + 3] + xv.w;
            *(float4*)(out + o) = res;
        }
        __syncthreads();
    }
}

// ---------------- launch ------------------------------------------------------
extern "C" void kernel_launch(void* const* d_in, const int* in_sizes, int n_in,
                              void* d_out, int out_size) {
    const float* x        = (const float*)d_in[0];
    const int*   task_ids = (const int*)d_in[1];
    const float* eps      = (const float*)d_in[2];
    const float* gate_w   = (const float*)d_in[3];
    const float* fc1_w    = (const float*)d_in[4];
    const float* fc1_b    = (const float*)d_in[5];
    const float* fc2_w    = (const float*)d_in[6];
    const float* fc2_b    = (const float*)d_in[7];
    float* out = (float*)d_out;

    cudaFuncSetAttribute(expert_kernel, cudaFuncAttributeMaxDynamicSharedMemorySize, SMEM_TOTAL);
    cudaFuncSetAttribute(gate_kernel, cudaFuncAttributeMaxDynamicSharedMemorySize, C_ * 16 * 4);

    convert_kernel<<<512, 256>>>(fc1_w, fc2_w);
    gate_kernel<<<dim3(B_, 8), 128, C_ * 16 * 4>>>(x, task_ids, eps, gate_w);
    expert_kernel<<<dim3(B_, N_ / TM), 256, SMEM_TOTAL>>>(x, fc1_b, fc2_b, out);
}

// round 11
// speedup vs baseline: 1.1259x; 1.0904x over previous
#include <cuda_runtime.h>
#include <cuda_bf16.h>
#include <mma.h>
#include <cstdint>

using namespace nvcuda;

#define B_ 16
#define N_ 1024
#define C_ 768
#define E_ 8
#define H_ 192
#define D_ 4
#define K_ 2

// ---------------- device scratch (no runtime allocation allowed) -------------
__device__ __nv_bfloat16 g_xbf[B_ * N_ * C_];     // x in bf16
__device__ __nv_bfloat16 g_w1bf[E_ * H_ * C_];    // fc1_w bf16 [E][H][C]
__device__ __nv_bfloat16 g_w2bf[E_ * C_ * H_];    // fc2_w bf16 [E][C][H]
__device__ float g_part[B_ * 8 * E_];

// ---------------- fp32 -> bf16 conversion (weights first, x last) -------------
__global__ void convert_kernel(const float* __restrict__ x,
                               const float* __restrict__ w1,
                               const float* __restrict__ w2) {
    int i = blockIdx.x * blockDim.x + threadIdx.x;
    int stride = gridDim.x * blockDim.x;
    const int nx4 = B_ * N_ * C_ / 4;
    const int nw4 = E_ * H_ * C_ / 4;
    for (int t = i; t < nw4; t += stride) {
        float4 v = ((const float4*)w1)[t];
        g_w1bf[4 * t + 0] = __float2bfloat16(v.x);
        g_w1bf[4 * t + 1] = __float2bfloat16(v.y);
        g_w1bf[4 * t + 2] = __float2bfloat16(v.z);
        g_w1bf[4 * t + 3] = __float2bfloat16(v.w);
    }
    for (int t = i; t < nw4; t += stride) {
        float4 v = ((const float4*)w2)[t];
        g_w2bf[4 * t + 0] = __float2bfloat16(v.x);
        g_w2bf[4 * t + 1] = __float2bfloat16(v.y);
        g_w2bf[4 * t + 2] = __float2bfloat16(v.z);
        g_w2bf[4 * t + 3] = __float2bfloat16(v.w);
    }
    for (int t = i; t < nx4; t += stride) {
        float4 v = ((const float4*)x)[t];
        g_xbf[4 * t + 0] = __float2bfloat16(v.x);
        g_xbf[4 * t + 1] = __float2bfloat16(v.y);
        g_xbf[4 * t + 2] = __float2bfloat16(v.z);
        g_xbf[4 * t + 3] = __float2bfloat16(v.w);
    }
}

// ---------------- gate kernel (R3 verbatim, measured 31.4us) -------------------
__global__ void gate_kernel(const float* __restrict__ x,
                            const int* __restrict__ task_ids,
                            const float* __restrict__ eps,
                            const float* __restrict__ gate_w) {
    extern __shared__ float s_gw[];            // [C_*16]
    __shared__ float s_red[4 * E_];
    int b = blockIdx.x;
    int n = blockIdx.y * 128 + threadIdx.x;
    int task = task_ids[b];

    const float4* gw4 = (const float4*)(gate_w + (size_t)task * C_ * 16);
    for (int i = threadIdx.x; i < C_ * 16 / 4; i += 128)
        ((float4*)s_gw)[i] = gw4[i];
    __syncthreads();

    float acc[16];
#pragma unroll
    for (int e = 0; e < 16; e++) acc[e] = 0.f;

    const float* xr = x + ((size_t)b * N_ + n) * C_;
    for (int c = 0; c < C_; c += 4) {
        float4 xv = *(const float4*)(xr + c);
#pragma unroll
        for (int e = 0; e < 16; e++) {
            acc[e] += xv.x * s_gw[(c + 0) * 16 + e];
            acc[e] += xv.y * s_gw[(c + 1) * 16 + e];
            acc[e] += xv.z * s_gw[(c + 2) * 16 + e];
            acc[e] += xv.w * s_gw[(c + 3) * 16 + e];
        }
    }

    float lg[E_];
    const float* er = eps + ((size_t)b * N_ + n) * E_;
#pragma unroll
    for (int e = 0; e < E_; e++) {
        float raw = acc[E_ + e];
        float sp = (raw > 15.f) ? raw : log1pf(expf(raw));
        lg[e] = acc[e] + er[e] * (sp + 0.01f);
    }

#pragma unroll
    for (int off = 16; off > 0; off >>= 1) {
#pragma unroll
        for (int e = 0; e < E_; e++)
            lg[e] += __shfl_down_sync(0xffffffffu, lg[e], off);
    }
    int warp = threadIdx.x >> 5, lane = threadIdx.x & 31;
    if (lane == 0) {
#pragma unroll
        for (int e = 0; e < E_; e++) s_red[warp * E_ + e] = lg[e];
    }
    __syncthreads();
    if (threadIdx.x < E_) {
        float s = s_red[threadIdx.x] + s_red[E_ + threadIdx.x] +
                  s_red[2 * E_ + threadIdx.x] + s_red[3 * E_ + threadIdx.x];
        g_part[((size_t)b * 8 + blockIdx.y) * E_ + threadIdx.x] = s;
    }
}

// ---------------- fused 2-expert adapter kernel (R3 + inline top-2 + s_bias) --
#define TM 128                 // rows per block
#define KC 64                  // k chunk (phase 1)
#define PA 72                  // smem pitch for A/B1 tiles (bf16 elems)
#define PH 200                 // smem pitch for h / B2 tiles (bf16 elems)
#define PF 132                 // smem pitch for f32 epilogue staging
#define PS 100                 // smem pitch for f32 phase-1 staging

// smem layout (bytes):
#define OFF_H0   0
#define OFF_H1   51200                       // 128*200*2
#define OFF_AB   102400
#define OFF_A0   (OFF_AB)
#define OFF_A1   (OFF_AB + 18432)            // 128*72*2
#define OFF_B0   (OFF_AB + 36864)
#define OFF_B1   (OFF_AB + 36864 + 27648)    // 192*72*2
#define SMEM_TOTAL (OFF_AB + 92160)          // 194560

__device__ __forceinline__ void cpasync16(void* dst, const void* src) {
    unsigned int d = (unsigned int)__cvta_generic_to_shared(dst);
    asm volatile("cp.async.cg.shared.global [%0], [%1], 16;\n" :: "r"(d), "l"(src));
}
__device__ __forceinline__ void cpcommit() {
    asm volatile("cp.async.commit_group;\n");
}
template <int Nw>
__device__ __forceinline__ void cpwait() {
    asm volatile("cp.async.wait_group %0;\n" :: "n"(Nw));
}

__global__ __launch_bounds__(256, 1)
void expert_kernel(const float* __restrict__ x,
                   const float* __restrict__ b1,
                   const float* __restrict__ b2,
                   float* __restrict__ out) {
    extern __shared__ char smem[];
    __nv_bfloat16* s_h[2] = { (__nv_bfloat16*)(smem + OFF_H0),
                              (__nv_bfloat16*)(smem + OFF_H1) };
    __nv_bfloat16* s_a[2] = { (__nv_bfloat16*)(smem + OFF_A0),
                              (__nv_bfloat16*)(smem + OFF_A1) };
    __nv_bfloat16* s_b[2] = { (__nv_bfloat16*)(smem + OFF_B0),
                              (__nv_bfloat16*)(smem + OFF_B1) };
    __nv_bfloat16* s_b2 = (__nv_bfloat16*)(smem + OFF_AB);   // phase2 W2 tile [128][PH]
    float* s_f = (float*)(smem + OFF_AB);                    // phase2 staging [128][PF]

    __shared__ int   s_sel[2];
    __shared__ float s_gvs[2];
    __shared__ float s_bias[C_];             // combined g0*b2[e0]+g1*b2[e1]

    const int b = blockIdx.x;
    const int row0 = blockIdx.y * TM;
    const int tid = threadIdx.x;
    const int w = tid >> 5;
    const int r = w >> 1;       // row quarter (32 rows each)
    const int hw = w & 1;       // column half

    // inline top-2 + softmax (validated in R10)
    if (tid == 0) {
        float s[E_];
#pragma unroll
        for (int e = 0; e < E_; e++) {
            float a = 0.f;
#pragma unroll
            for (int blk = 0; blk < 8; blk++) a += g_part[(b * 8 + blk) * E_ + e];
            s[e] = a;
        }
        int i1 = 0;
#pragma unroll
        for (int e = 1; e < E_; e++) if (s[e] > s[i1]) i1 = e;
        int i2 = (i1 == 0) ? 1 : 0;
#pragma unroll
        for (int e = 0; e < E_; e++) if (e != i1 && s[e] > s[i2]) i2 = e;
        float v1 = s[i1], v2 = s[i2];
        float sc = (v1 - v2) / ((v1 - v2) + 1e-6f);
        float e1 = expf(sc);
        s_sel[0] = i1;
        s_sel[1] = i2;
        s_gvs[0] = e1 / (e1 + 1.f);
        s_gvs[1] = 1.f / (e1 + 1.f);
    }
    __syncthreads();

    const int e0 = s_sel[0], e1 = s_sel[1];
    const float g0 = s_gvs[0], g1 = s_gvs[1];
    const int eid[2] = { e0, e1 };
    const float gg[2] = { g0, g1 };

    // combined output bias (used by phase-2 epilogue; synced well before use)
    for (int i = tid; i < C_; i += 256)
        s_bias[i] = g0 * b2[e0 * C_ + i] + g1 * b2[e1 * C_ + i];

    // ================= phase 1: h_e = g_e * gelu(x @ W1_e^T + b1_e) ==========
    for (int ke = 0; ke < 2; ke++) {
        const int e = eid[ke];
        const __nv_bfloat16* xsrc = g_xbf + ((size_t)(b * N_ + row0)) * C_;
        const __nv_bfloat16* wsrc = g_w1bf + (size_t)e * H_ * C_;

        // preload chunk 0
        {
#pragma unroll
            for (int i = 0; i < 4; i++) {
                int seg = tid + i * 256;                 // 0..1023
                int row = seg >> 3, so = (seg & 7) * 8;
                cpasync16(s_a[0] + row * PA + so, xsrc + (size_t)row * C_ + so);
            }
#pragma unroll
            for (int i = 0; i < 6; i++) {
                int seg = tid + i * 256;                 // 0..1535
                int row = seg >> 3, so = (seg & 7) * 8;
                cpasync16(s_b[0] + row * PA + so, wsrc + (size_t)row * C_ + so);
            }
            cpcommit();
        }

        wmma::fragment<wmma::accumulator, 16, 16, 16, float> acc[2][6];
#pragma unroll
        for (int i = 0; i < 2; i++)
#pragma unroll
            for (int j = 0; j < 6; j++) wmma::fill_fragment(acc[i][j], 0.f);

        for (int t = 0; t < C_ / KC; t++) {
            int cur = t & 1;
            if (t + 1 < C_ / KC) {
                int nxt = cur ^ 1, kc = (t + 1) * KC;
#pragma unroll
                for (int i = 0; i < 4; i++) {
                    int seg = tid + i * 256;
                    int row = seg >> 3, so = (seg & 7) * 8;
                    cpasync16(s_a[nxt] + row * PA + so, xsrc + (size_t)row * C_ + kc + so);
                }
#pragma unroll
                for (int i = 0; i < 6; i++) {
                    int seg = tid + i * 256;
                    int row = seg >> 3, so = (seg & 7) * 8;
                    cpasync16(s_b[nxt] + row * PA + so, wsrc + (size_t)row * C_ + kc + so);
                }
                cpcommit();
                cpwait<1>();
            } else {
                cpwait<0>();
            }
            __syncthreads();

#pragma unroll
            for (int kk = 0; kk < KC / 16; kk++) {
                wmma::fragment<wmma::matrix_a, 16, 16, 16, __nv_bfloat16, wmma::row_major> aF[2];
#pragma unroll
                for (int i = 0; i < 2; i++)
                    wmma::load_matrix_sync(aF[i], s_a[cur] + (r * 32 + i * 16) * PA + kk * 16, PA);
#pragma unroll
                for (int j = 0; j < 6; j++) {
                    wmma::fragment<wmma::matrix_b, 16, 16, 16, __nv_bfloat16, wmma::col_major> bF;
                    wmma::load_matrix_sync(bF, s_b[cur] + (hw * 96 + j * 16) * PA + kk * 16, PA);
#pragma unroll
                    for (int i = 0; i < 2; i++)
                        wmma::mma_sync(acc[i][j], aF[i], bF, acc[i][j]);
                }
            }
            __syncthreads();
        }

        // stage -> bias + gelu + gate-scale -> bf16 into s_h[ke]
        float* stg = (ke == 0) ? (float*)(smem + OFF_H1) : (float*)(smem + OFF_AB);
        const float gsc = gg[ke];
#pragma unroll
        for (int half = 0; half < 2; half++) {
            if (hw == half) {
#pragma unroll
                for (int i = 0; i < 2; i++)
#pragma unroll
                    for (int j = 0; j < 6; j++)
                        wmma::store_matrix_sync(stg + (r * 32 + i * 16) * PS + j * 16,
                                                acc[i][j], PS, wmma::mem_row_major);
            }
            __syncthreads();
            for (int idx = tid; idx < TM * 96; idx += 256) {
                int n = idx / 96, hh = idx % 96;
                int hcol = half * 96 + hh;
                float v = stg[n * PS + hh] + b1[e * H_ + hcol];
                float gel = 0.5f * v * (1.f + erff(v * 0.70710678118f));
                s_h[ke][n * PH + hcol] = __float2bfloat16(gsc * gel);
            }
            __syncthreads();
        }
    }

    // ================= phase 2: out = x + sum_e h_e @ W2_e^T + bias ==========
    for (int cc = 0; cc < C_; cc += 128) {
        wmma::fragment<wmma::accumulator, 16, 16, 16, float> acc2[2][4];
#pragma unroll
        for (int i = 0; i < 2; i++)
#pragma unroll
            for (int j = 0; j < 4; j++) wmma::fill_fragment(acc2[i][j], 0.f);

        for (int ke = 0; ke < 2; ke++) {
            const int e = eid[ke];
            __syncthreads();   // s_ab free (prev epilogue / prev expert k-loop done)
            const __nv_bfloat16* wsrc = g_w2bf + (size_t)e * C_ * H_ + (size_t)cc * H_;
#pragma unroll
            for (int i = 0; i < 12; i++) {
                int seg = tid + i * 256;                 // 0..3071
                int row = seg / 24, so = (seg % 24) * 8;
                cpasync16(s_b2 + row * PH + so, wsrc + (size_t)row * H_ + so);
            }
            cpcommit();
            cpwait<0>();
            __syncthreads();

#pragma unroll
            for (int kk = 0; kk < H_ / 16; kk++) {
                wmma::fragment<wmma::matrix_a, 16, 16, 16, __nv_bfloat16, wmma::row_major> aF[2];
#pragma unroll
                for (int i = 0; i < 2; i++)
                    wmma::load_matrix_sync(aF[i], s_h[ke] + (r * 32 + i * 16) * PH + kk * 16, PH);
#pragma unroll
                for (int j = 0; j < 4; j++) {
                    wmma::fragment<wmma::matrix_b, 16, 16, 16, __nv_bfloat16, wmma::col_major> bF;
                    wmma::load_matrix_sync(bF, s_b2 + (hw * 64 + j * 16) * PH + kk * 16, PH);
#pragma unroll
                    for (int i = 0; i < 2; i++)
                        wmma::mma_sync(acc2[i][j], aF[i], bF, acc2[i][j]);
                }
            }
        }
        __syncthreads();
#pragma unroll
        for (int i = 0; i < 2; i++)
#pragma unroll
            for (int j = 0; j < 4; j++)
                wmma::store_matrix_sync(s_f + (r * 32 + i * 16) * PF + hw * 64 + j * 16,
                                        acc2[i][j], PF, wmma::mem_row_major);
        __syncthreads();

#pragma unroll
        for (int it = 0; it < 16; it++) {
            int idx = tid + it * 256;                    // 0..4095
            int row = idx >> 5, q = idx & 31;
            int c = cc + q * 4;
            size_t o = ((size_t)(b * N_ + row0 + row)) * C_ + c;
            float4 xv = *(const float4*)(x + o);
            float4 bv = *(const float4*)(s_bias + c);
            float4 res;
            res.x = s_f[row * PF + q * 4 + 0] + bv.x + xv.x;
            res.y = s_f[row * PF + q * 4 + 1] + bv.y + xv.y;
            res.z = s_f[row * PF + q * 4 + 2] + bv.z + xv.z;
            res.w = s_f[row * PF + q * 4 + 3] + bv.w + xv.w;
            *(float4*)(out + o) = res;
        }
        __syncthreads();
    }
}

// ---------------- launch ------------------------------------------------------
extern "C" void kernel_launch(void* const* d_in, const int* in_sizes, int n_in,
                              void* d_out, int out_size) {
    const float* x        = (const float*)d_in[0];
    const int*   task_ids = (const int*)d_in[1];
    const float* eps      = (const float*)d_in[2];
    const float* gate_w   = (const float*)d_in[3];
    const float* fc1_w    = (const float*)d_in[4];
    const float* fc1_b    = (const float*)d_in[5];
    const float* fc2_w    = (const float*)d_in[6];
    const float* fc2_b    = (const float*)d_in[7];
    float* out = (float*)d_out;

    cudaFuncSetAttribute(expert_kernel, cudaFuncAttributeMaxDynamicSharedMemorySize, SMEM_TOTAL);
    cudaFuncSetAttribute(gate_kernel, cudaFuncAttributeMaxDynamicSharedMemorySize, C_ * 16 * 4);

    convert_kernel<<<1024, 256>>>(x, fc1_w, fc2_w);
    gate_kernel<<<dim3(B_, 8), 128, C_ * 16 * 4>>>(x, task_ids, eps, gate_w);
    expert_kernel<<<dim3(B_, N_ / TM), 256, SMEM_TOTAL>>>(x, fc1_b, fc2_b, out);
}